// round 16
// baseline (speedup 1.0000x reference)
#include <cuda_runtime.h>
#include <cuda_bf16.h>
#include <cuda_fp16.h>
#include <cstdint>
#include <math.h>

#define BB 64
#define NNN 1024
#define CCC 256
#define KKK 512
#define NPAIR 128

__device__ float g_F[(size_t)BB * KKK * CCC];
__device__ __nv_bfloat16 g_Fh[(size_t)BB * KKK * CCC];
__device__ __nv_bfloat16 g_Fl[(size_t)BB * KKK * CCC];
__device__ float              g_hmin[(size_t)NPAIR * KKK * 8];
__device__ unsigned long long g_hmask[(size_t)NPAIR * KKK * 8];
__device__ float g_norm2[BB * KKK];
__device__ float g_cx[BB * KKK];
__device__ float g_cy[BB * KKK];
__device__ float g_cz[BB * KKK];
__device__ int   g_idx[BB * KKK];
__device__ int   g_neff[BB];
__device__ int   g_corr[NPAIR * KKK];
__device__ float g_s[NPAIR * KKK];

__device__ __forceinline__ uint32_t smem_u32(const void* p) {
    uint32_t a;
    asm("{ .reg .u64 t; cvta.to.shared.u64 t, %1; cvt.u32.u64 %0, t; }" : "=r"(a) : "l"(p));
    return a;
}
__device__ __forceinline__ void cp_async16(uint32_t saddr, const void* g) {
    asm volatile("cp.async.cg.shared.global [%0], [%1], 16;" :: "r"(saddr), "l"(g));
}
#define CP_COMMIT() asm volatile("cp.async.commit_group;" ::: "memory")

#define LDSM_X4(R0, R1, R2, R3, ADDR) \
    asm volatile("ldmatrix.sync.aligned.m8n8.x4.shared.b16 {%0,%1,%2,%3}, [%4];" \
        : "=r"(R0), "=r"(R1), "=r"(R2), "=r"(R3) : "r"(ADDR))

#define MMA_BF16(D, A, B0, B1) \
    asm volatile("mma.sync.aligned.m16n8k16.row.col.f32.bf16.bf16.f32 " \
        "{%0,%1,%2,%3}, {%4,%5,%6,%7}, {%8,%9}, {%0,%1,%2,%3};" \
        : "+f"((D)[0]), "+f"((D)[1]), "+f"((D)[2]), "+f"((D)[3]) \
        : "r"((A)[0]), "r"((A)[1]), "r"((A)[2]), "r"((A)[3]), "r"(B0), "r"(B1))

#define DELTA 3.0f

// ---- kernel 0: per-batch top-K via bitonic sort on (-attn, idx); zeroes g_norm2 ----
__global__ __launch_bounds__(1024) void topk_kernel(
    const float* __restrict__ attn, const int* __restrict__ num_rt,
    const float* __restrict__ cents, const float* __restrict__ sns)
{
    __shared__ float skey[NNN];
    __shared__ int   sidx[NNN];
    const int b = blockIdx.x, tid = threadIdx.x;
    const int nr = num_rt[b];
    if (tid < KKK) g_norm2[b * KKK + tid] = 0.f;
    skey[tid] = (tid < nr) ? attn[b * NNN + tid] : -1000000000.0f;
    sidx[tid] = tid;
    __syncthreads();
    for (int size = 2; size <= NNN; size <<= 1)
        for (int stride = size >> 1; stride > 0; stride >>= 1) {
            int j = tid ^ stride;
            if (j > tid) {
                float k1 = skey[tid], k2 = skey[j];
                int   i1 = sidx[tid], i2 = sidx[j];
                bool g  = (k1 < k2) || (k1 == k2 && i1 > i2);
                bool dd = ((tid & size) == 0);
                if (g == dd) { skey[tid] = k2; skey[j] = k1; sidx[tid] = i2; sidx[j] = i1; }
            }
            __syncthreads();
        }
    if (tid < KKK) {
        int i = sidx[tid];
        g_idx[b * KKK + tid] = i;
        float sc = sns[b * 4 + 3];
        float cx = cents[(b * NNN + i) * 3 + 0];
        float cy = cents[(b * NNN + i) * 3 + 1];
        float cz = cents[(b * NNN + i) * 3 + 2];
        if (i < nr) {
            cx = cx * sc + sns[b * 4 + 0];
            cy = cy * sc + sns[b * 4 + 1];
            cz = cz * sc + sns[b * 4 + 2];
        }
        g_cx[b * KKK + tid] = cx;
        g_cy[b * KKK + tid] = cy;
        g_cz[b * KKK + tid] = cz;
    }
    if (tid == 0) g_neff[b] = (nr < KKK) ? nr : KKK;
}

// ---- kernel 1: F = gather(rt) @ W_in + b_in (fp32 SIMT, double-buffered) ----
__global__ __launch_bounds__(256) void gemmF_kernel(
    const float* __restrict__ rt, const float* __restrict__ Win,
    const float* __restrict__ bin)
{
    __shared__ float As[2][16][128];
    __shared__ float Bs[2][16][128];
    const int tid = threadIdx.x;
    const int r0 = blockIdx.y * 128;
    const int c0 = blockIdx.x * 128;
    const int tx = tid & 15, ty = tid >> 4;
    const int lrow = tid >> 1, lc = (tid & 1) * 4;
    const int grow = r0 + lrow;
    const float* arow = rt + ((size_t)(grow >> 9) * NNN + g_idx[grow]) * CCC;
    const int q0 = tid, q1 = tid + 256;
    const float* wp0 = Win + (size_t)(q0 >> 5) * CCC + c0 + (q0 & 31) * 4;
    const float* wp1 = Win + (size_t)(q1 >> 5) * CCC + c0 + (q1 & 31) * 4;

    float acc[8][8];
#pragma unroll
    for (int i = 0; i < 8; i++)
#pragma unroll
        for (int j = 0; j < 8; j++) acc[i][j] = 0.f;

    float4 a0 = *(const float4*)(arow + lc);
    float4 a1 = *(const float4*)(arow + lc + 8);
    float4 b0 = *(const float4*)(wp0);
    float4 b1 = *(const float4*)(wp1);

    {
        float (*A)[128] = As[0]; float (*Bb)[128] = Bs[0];
        A[lc + 0][lrow] = a0.x; A[lc + 1][lrow] = a0.y;
        A[lc + 2][lrow] = a0.z; A[lc + 3][lrow] = a0.w;
        A[lc + 8][lrow] = a1.x; A[lc + 9][lrow] = a1.y;
        A[lc +10][lrow] = a1.z; A[lc +11][lrow] = a1.w;
        *(float4*)&Bb[q0 >> 5][(q0 & 31) * 4] = b0;
        *(float4*)&Bb[q1 >> 5][(q1 & 31) * 4] = b1;
    }

    for (int it = 0; it < 16; it++) {
        __syncthreads();
        const int buf = it & 1;
        if (it + 1 < 16) {
            const int cN = (it + 1) * 16;
            a0 = *(const float4*)(arow + cN + lc);
            a1 = *(const float4*)(arow + cN + lc + 8);
            b0 = *(const float4*)(wp0 + (size_t)cN * CCC);
            b1 = *(const float4*)(wp1 + (size_t)cN * CCC);
        }
#pragma unroll
        for (int kk = 0; kk < 16; kk++) {
            float ra[8], rb[8];
            *(float4*)&ra[0] = *(const float4*)&As[buf][kk][ty * 8];
            *(float4*)&ra[4] = *(const float4*)&As[buf][kk][ty * 8 + 4];
            *(float4*)&rb[0] = *(const float4*)&Bs[buf][kk][tx * 8];
            *(float4*)&rb[4] = *(const float4*)&Bs[buf][kk][tx * 8 + 4];
#pragma unroll
            for (int i = 0; i < 8; i++)
#pragma unroll
                for (int j = 0; j < 8; j++) acc[i][j] += ra[i] * rb[j];
        }
        if (it + 1 < 16) {
            float (*A)[128] = As[buf ^ 1]; float (*Bb)[128] = Bs[buf ^ 1];
            A[lc + 0][lrow] = a0.x; A[lc + 1][lrow] = a0.y;
            A[lc + 2][lrow] = a0.z; A[lc + 3][lrow] = a0.w;
            A[lc + 8][lrow] = a1.x; A[lc + 9][lrow] = a1.y;
            A[lc +10][lrow] = a1.z; A[lc +11][lrow] = a1.w;
            *(float4*)&Bb[q0 >> 5][(q0 & 31) * 4] = b0;
            *(float4*)&Bb[q1 >> 5][(q1 & 31) * 4] = b1;
        }
    }
#pragma unroll
    for (int i = 0; i < 8; i++) {
        size_t off = (size_t)(r0 + ty * 8 + i) * CCC + c0 + tx * 8;
        float* dst = g_F + off;
        __nv_bfloat16 hi8[8], lo8[8];
        float ps = 0.f;
#pragma unroll
        for (int j = 0; j < 8; j++) {
            float v = acc[i][j] + bin[c0 + tx * 8 + j];
            dst[j] = v;
            ps += v * v;
            __nv_bfloat16 h = __float2bfloat16(v);
            hi8[j] = h;
            lo8[j] = __float2bfloat16(v - __bfloat162float(h));
        }
        *(uint4*)(g_Fh + off) = *(const uint4*)hi8;
        *(uint4*)(g_Fl + off) = *(const uint4*)lo8;
#pragma unroll
        for (int m = 1; m <= 8; m <<= 1) ps += __shfl_xor_sync(0xffffffffu, ps, m);
        if (tx == 0) atomicAdd(&g_norm2[r0 + ty * 8 + i], ps);
    }
}

// ---- kernel 2: fused 2-pass bf16-split GEMM, 1 sync per chunk ----
#define LDA 40
#define STG (128 * LDA)
#define GDYN_SMEM (9 * STG * 2 + 512)
__global__ __launch_bounds__(256, 2) void gemmG_mma_kernel(
    const int* __restrict__ anc, const int* __restrict__ pos,
    const int* __restrict__ neg)
{
    extern __shared__ char smem[];
    __nv_bfloat16* sAh = (__nv_bfloat16*)smem;
    __nv_bfloat16* sAl = sAh + 3 * STG;
    __nv_bfloat16* sB  = sAh + 6 * STG;
    float* snorm = (float*)(sAh + 9 * STG);

    const int tid = threadIdx.x, lane = tid & 31, wid = tid >> 5;
    const int p = blockIdx.x, mtile = blockIdx.y, ntile = blockIdx.z;
    const int t = p >> 1;
    const int a = anc[t];
    const int c = (p & 1) ? neg[t] : pos[t];

    if (tid < 128) snorm[tid] = g_norm2[c * KKK + ntile * 128 + tid];

    const int m_base = (wid >> 1) * 32;
    const int n_base = (wid & 1) * 64;

    float acc[2][8][4];
#pragma unroll
    for (int mi = 0; mi < 2; mi++)
#pragma unroll
        for (int n8 = 0; n8 < 8; n8++)
#pragma unroll
            for (int r = 0; r < 4; r++) acc[mi][n8][r] = 0.f;

    const int ld_row = tid >> 2, ld_q = (tid & 3) * 8;
    const __nv_bfloat16* gAhi = g_Fh + (size_t)(a * KKK + mtile * 128) * CCC;
    const __nv_bfloat16* gAlo = g_Fl + (size_t)(a * KKK + mtile * 128) * CCC;
    const __nv_bfloat16* gB   = g_Fh + (size_t)(c * KKK + ntile * 128) * CCC;
    const size_t go1 = (size_t)ld_row * CCC + ld_q;
    const size_t go2 = (size_t)(ld_row + 64) * CCC + ld_q;
    const uint32_t so1 = (uint32_t)((ld_row * LDA + ld_q) * 2);
    const uint32_t so2 = (uint32_t)(((ld_row + 64) * LDA + ld_q) * 2);
    const uint32_t sAhu = smem_u32(sAh);
    const uint32_t sAlu = smem_u32(sAl);
    const uint32_t sBu  = smem_u32(sB);

#define ISSUE(KC, ST) do { \
        const int c0 = (KC) * 32; \
        uint32_t dAh = sAhu + (uint32_t)(ST) * (STG * 2); \
        uint32_t dAl = sAlu + (uint32_t)(ST) * (STG * 2); \
        uint32_t dB  = sBu  + (uint32_t)(ST) * (STG * 2); \
        cp_async16(dAh + so1, gAhi + go1 + c0); \
        cp_async16(dAl + so1, gAlo + go1 + c0); \
        cp_async16(dB  + so1, gB   + go1 + c0); \
        cp_async16(dAh + so2, gAhi + go2 + c0); \
        cp_async16(dAl + so2, gAlo + go2 + c0); \
        cp_async16(dB  + so2, gB   + go2 + c0); \
        CP_COMMIT(); \
    } while (0)

    ISSUE(0, 0);
    ISSUE(1, 1);
    for (int kc = 0; kc < 8; kc++) {
        const int buf = kc % 3;
        if (kc < 7) {
            asm volatile("cp.async.wait_group 1;" ::: "memory");
        } else {
            asm volatile("cp.async.wait_group 0;" ::: "memory");
        }
        __syncthreads();
        if (kc + 2 < 8) ISSUE(kc + 2, (kc + 2) % 3);
        const uint32_t sah = sAhu + (uint32_t)buf * (STG * 2);
        const uint32_t sal = sAlu + (uint32_t)buf * (STG * 2);
        const uint32_t sb  = sBu  + (uint32_t)buf * (STG * 2);
#pragma unroll
        for (int ks = 0; ks < 2; ks++) {
            const int k0 = ks * 16;
            const uint32_t arow_off = (uint32_t)(((m_base + (lane & 15)) * LDA + k0 + (lane >> 4) * 8) << 1);
            uint32_t afh[2][4], afl[2][4];
#pragma unroll
            for (int mi = 0; mi < 2; mi++) {
                LDSM_X4(afh[mi][0], afh[mi][1], afh[mi][2], afh[mi][3],
                        sah + arow_off + (uint32_t)((mi * 16 * LDA) << 1));
                LDSM_X4(afl[mi][0], afl[mi][1], afl[mi][2], afl[mi][3],
                        sal + arow_off + (uint32_t)((mi * 16 * LDA) << 1));
            }
            uint32_t bfr[4][4];
#pragma unroll
            for (int nj = 0; nj < 4; nj++) {
                uint32_t addr = sb + (uint32_t)(((n_base + nj * 16 + (lane & 7) + ((lane >> 4) << 3)) * LDA + k0 + ((lane >> 3) & 1) * 8) << 1);
                LDSM_X4(bfr[nj][0], bfr[nj][1], bfr[nj][2], bfr[nj][3], addr);
            }
#pragma unroll
            for (int mi = 0; mi < 2; mi++)
#pragma unroll
                for (int n8 = 0; n8 < 8; n8++) {
                    MMA_BF16(acc[mi][n8], afh[mi], bfr[n8 >> 1][(n8 & 1) * 2], bfr[n8 >> 1][(n8 & 1) * 2 + 1]);
                    MMA_BF16(acc[mi][n8], afl[mi], bfr[n8 >> 1][(n8 & 1) * 2], bfr[n8 >> 1][(n8 & 1) * 2 + 1]);
                }
        }
        __syncthreads();
    }
#undef ISSUE

#pragma unroll
    for (int mi = 0; mi < 2; mi++)
#pragma unroll
        for (int half = 0; half < 2; half++) {
            float kv[16];
            float kmin = 3.4e38f;
            const int lc0 = n_base + (lane & 3) * 2;
#pragma unroll
            for (int n8 = 0; n8 < 8; n8++) {
                float k0v = snorm[lc0 + n8 * 8]     - 2.f * acc[mi][n8][half * 2 + 0];
                float k1v = snorm[lc0 + n8 * 8 + 1] - 2.f * acc[mi][n8][half * 2 + 1];
                kv[n8 * 2]     = k0v;
                kv[n8 * 2 + 1] = k1v;
                kmin = fminf(kmin, fminf(k0v, k1v));
            }
            kmin = fminf(kmin, __shfl_xor_sync(0xffffffffu, kmin, 1));
            kmin = fminf(kmin, __shfl_xor_sync(0xffffffffu, kmin, 2));
            const float thr = kmin + DELTA;
            unsigned long long mk = 0ull;
#pragma unroll
            for (int n8 = 0; n8 < 8; n8++) {
                if (kv[n8 * 2]     <= thr) mk |= 1ull << (n8 * 8 + (lane & 3) * 2);
                if (kv[n8 * 2 + 1] <= thr) mk |= 1ull << (n8 * 8 + (lane & 3) * 2 + 1);
            }
            mk |= __shfl_xor_sync(0xffffffffu, mk, 1);
            mk |= __shfl_xor_sync(0xffffffffu, mk, 2);
            if ((lane & 3) == 0) {
                int grow = mtile * 128 + m_base + mi * 16 + half * 8 + (lane >> 2);
                int hidx = ntile * 2 + (wid & 1);
                size_t o = ((size_t)p * KKK + grow) * 8 + hidx;
                g_hmin[o]  = kmin;
                g_hmask[o] = mk;
            }
        }
}

// ---- kernel 2b: exact argmin, all loads hoisted (1 warp per row) ----
__global__ __launch_bounds__(256) void refine_kernel(
    const int* __restrict__ anc, const int* __restrict__ pos,
    const int* __restrict__ neg)
{
    const int p = blockIdx.x, tid = threadIdx.x;
    const int t = p >> 1;
    const int a = anc[t];
    const int c = (p & 1) ? neg[t] : pos[t];
    const int wid = tid >> 5, lane = tid & 31;
    const float* nrm = g_norm2 + c * KKK;

    const int r = blockIdx.y * 8 + wid;
    const size_t base = ((size_t)p * KKK + r) * 8;

    const float* fa = g_F + ((size_t)a * KKK + r) * CCC;
    const float4 fa0 = ((const float4*)fa)[lane * 2];
    const float4 fa1 = ((const float4*)fa)[lane * 2 + 1];
    float hm = (lane < 8) ? g_hmin[base + lane] : 3.4e38f;
    unsigned long long hmk = (lane < 8) ? g_hmask[base + lane] : 0ull;

    float bk = hm;
#pragma unroll
    for (int m = 4; m >= 1; m >>= 1) bk = fminf(bk, __shfl_xor_sync(0xffffffffu, bk, m));
    bk = __shfl_sync(0xffffffffu, bk, 0);
    const float thr = bk + DELTA;

    float bestk = 3.4e38f; int bestc = 0; float bestd = 0.f;
#pragma unroll 1
    for (int h = 0; h < 8; h++) {
        float mh = __shfl_sync(0xffffffffu, hm, h);
        if (mh > thr) continue;
        unsigned long long mk = __shfl_sync(0xffffffffu, hmk, h);
        const int colbase = h * 64;
        while (mk) {
            int b = __ffsll(mk) - 1; mk &= mk - 1;
            int col = colbase + b;
            const float4* fb4 = (const float4*)(g_F + ((size_t)c * KKK + col) * CCC);
            float4 fb0 = fb4[lane * 2];
            float4 fb1 = fb4[lane * 2 + 1];
            float sd = fa0.x * fb0.x + fa0.y * fb0.y + fa0.z * fb0.z + fa0.w * fb0.w
                     + fa1.x * fb1.x + fa1.y * fb1.y + fa1.z * fb1.z + fa1.w * fb1.w;
#pragma unroll
            for (int mm = 16; mm >= 1; mm >>= 1) sd += __shfl_xor_sync(0xffffffffu, sd, mm);
            float ek = nrm[col] - 2.f * sd;
            if (ek < bestk) { bestk = ek; bestc = col; bestd = sd; }
        }
    }
    if (lane == 0) {
        float na = sqrtf(g_norm2[a * KKK + r]);
        float nb = sqrtf(nrm[bestc]);
        g_s[p * KKK + r]    = fmaxf(bestd / (na * nb + 1e-8f), 0.f);
        g_corr[p * KKK + r] = bestc;
    }
}

// ---- kernel 3: geo bitmask (sqrt-free) + power iteration (set-bit) + sort + MLP ----
__global__ __launch_bounds__(512) void pair_kernel(
    const int* __restrict__ anc, const int* __restrict__ pos,
    const int* __restrict__ neg,
    const float* __restrict__ W1, const float* __restrict__ b1,
    const float* __restrict__ W2, const float* __restrict__ b2,
    float* __restrict__ out, int out_size)
{
    __shared__ unsigned int smask[KKK * 16];
    __shared__ float bufA[KKK * 3];
    __shared__ float bufB[KKK * 3];
    __shared__ float red[16];

    const int p = blockIdx.x, tid = threadIdx.x;
    const int t = p >> 1, n = p & 1;
    const int a = anc[t];
    const int c = n ? neg[t] : pos[t];
    const int neffa = g_neff[a], neffc = g_neff[c];
    const int wid = tid >> 5, lane = tid & 31;

    bufA[tid]           = g_cx[a * KKK + tid];
    bufA[KKK + tid]     = g_cy[a * KKK + tid];
    bufA[2 * KKK + tid] = g_cz[a * KKK + tid];
    {
        int j = g_corr[p * KKK + tid];
        bufB[tid]           = g_cx[c * KKK + j];
        bufB[KKK + tid]     = g_cy[c * KKK + j];
        bufB[2 * KKK + tid] = g_cz[c * KKK + j];
    }
    float sk = g_s[p * KKK + tid];
    __syncthreads();

    // geo test without sqrt: |sqrt(x)-sqrt(y)| < 0.5  <=>  s<0 || s^2 < 4xy, s=x+y-0.25
    for (int kr = 0; kr < 32; kr++) {
        int k = wid * 32 + kr;
        float akx = bufA[k], aky = bufA[KKK + k], akz = bufA[2 * KKK + k];
        float qkx = bufB[k], qky = bufB[KKK + k], qkz = bufB[2 * KKK + k];
        bool rowvalid = (k < neffa);
#pragma unroll 4
        for (int ch = 0; ch < 16; ch++) {
            int l = ch * 32 + lane;
            float dx = akx - bufA[l], dy = aky - bufA[KKK + l], dz = akz - bufA[2 * KKK + l];
            float x = dx * dx + dy * dy + dz * dz + 1e-12f;
            float ex = qkx - bufB[l], ey = qky - bufB[KKK + l], ez = qkz - bufB[2 * KKK + l];
            float y = ex * ex + ey * ey + ez * ez + 1e-12f;
            float s = x + y - 0.25f;
            bool near = (s < 0.f) || (s * s < 4.f * x * y);
            bool geo = near && rowvalid && (l < neffc) && (l != k);
            unsigned bits = __ballot_sync(0xffffffffu, geo);
            if (lane == 0) smask[k * 16 + ch] = bits;
        }
    }
    __syncthreads();

    float* sm_u = bufA;
    float v = (float)(1.0 / sqrt((double)KKK));
    for (int it = 0; it < 20; it++) {
        sm_u[tid] = sk * v;
        __syncthreads();
        float a0 = 0.f, a1 = 0.f, a2 = 0.f, a3 = 0.f;
        const unsigned* mrow = &smask[tid * 16];
#pragma unroll 4
        for (int w = 0; w < 16; w++) {
            unsigned bits = mrow[w];
            const float* up = sm_u + w * 32;
            float lacc = 0.f;
            while (bits) {
                int b = __ffs(bits) - 1;
                bits &= bits - 1;
                lacc += up[b];
            }
            switch (w & 3) {
                case 0: a0 += lacc; break;
                case 1: a1 += lacc; break;
                case 2: a2 += lacc; break;
                default: a3 += lacc; break;
            }
        }
        float wv = sk * ((a0 + a1) + (a2 + a3));
        float ss = wv * wv;
#pragma unroll
        for (int m = 16; m >= 1; m >>= 1) ss += __shfl_xor_sync(0xffffffffu, ss, m);
        if (lane == 0) red[wid] = ss;
        __syncthreads();
        float tot = 0.f;
#pragma unroll
        for (int w = 0; w < 16; w++) tot += red[w];
        v = wv / (sqrtf(tot) + 1e-8f);
    }

    float* sv = bufB;
    __syncthreads();
    sv[tid] = v;
    __syncthreads();
    for (int size = 2; size <= KKK; size <<= 1)
        for (int stride = size >> 1; stride > 0; stride >>= 1) {
            int jj = tid ^ stride;
            if (jj > tid) {
                float x1 = sv[tid], x2 = sv[jj];
                bool g  = (x1 < x2);
                bool dd = ((tid & size) == 0);
                if (g == dd) { sv[tid] = x2; sv[jj] = x1; }
            }
            __syncthreads();
        }

    float hacc = b1[tid];
    {
        const float4* sv4 = (const float4*)sv;
#pragma unroll 4
        for (int l4 = 0; l4 < 128; l4++) {
            float4 e = sv4[l4];
            hacc += e.x * W1[(size_t)(l4 * 4 + 0) * KKK + tid];
            hacc += e.y * W1[(size_t)(l4 * 4 + 1) * KKK + tid];
            hacc += e.z * W1[(size_t)(l4 * 4 + 2) * KKK + tid];
            hacc += e.w * W1[(size_t)(l4 * 4 + 3) * KKK + tid];
        }
    }
    float h = fmaxf(hacc, 0.f);
    float contrib = h * W2[tid];
#pragma unroll
    for (int m = 16; m >= 1; m >>= 1) contrib += __shfl_xor_sync(0xffffffffu, contrib, m);
    if (lane == 0) red[wid] = contrib;
    __syncthreads();
    if (tid == 0) {
        float x = 0.f;
        for (int w = 0; w < 16; w++) x += red[w];
        float score = 1.f / (1.f + expf(-(x + b2[0])));
        out[p] = score;
        if (NPAIR + p < out_size) out[NPAIR + p] = (n == 0) ? 1.f : 0.f;
    }
}

extern "C" void kernel_launch(void* const* d_in, const int* in_sizes, int n_in,
                              void* d_out, int out_size) {
    const float* rt    = (const float*)d_in[0];
    const float* cents = (const float*)d_in[1];
    const float* attn  = (const float*)d_in[2];
    const float* sns   = (const float*)d_in[3];
    const int*   nrt   = (const int*)d_in[4];
    const int*   anc   = (const int*)d_in[5];
    const int*   pos   = (const int*)d_in[6];
    const int*   neg   = (const int*)d_in[7];
    const float* Win   = (const float*)d_in[8];
    const float* bin   = (const float*)d_in[9];
    const float* W1    = (const float*)d_in[10];
    const float* b1    = (const float*)d_in[11];
    const float* W2    = (const float*)d_in[12];
    const float* b2    = (const float*)d_in[13];
    float* out = (float*)d_out;

    cudaFuncSetAttribute(gemmG_mma_kernel, cudaFuncAttributeMaxDynamicSharedMemorySize, GDYN_SMEM);

    topk_kernel<<<BB, 1024>>>(attn, nrt, cents, sns);
    gemmF_kernel<<<dim3(CCC / 128, BB * KKK / 128), 256>>>(rt, Win, bin);
    gemmG_mma_kernel<<<dim3(NPAIR, 4, 4), 256, GDYN_SMEM>>>(anc, pos, neg);
    refine_kernel<<<dim3(NPAIR, 64), 256>>>(anc, pos, neg);
    pair_kernel<<<NPAIR, 512>>>(anc, pos, neg, W1, b1, W2, b2, out, out_size);
}

// round 17
// speedup vs baseline: 2.1925x; 2.1925x over previous
#include <cuda_runtime.h>
#include <cuda_bf16.h>
#include <cuda_fp16.h>
#include <cstdint>
#include <math.h>

#define BB 64
#define NNN 1024
#define CCC 256
#define KKK 512
#define NPAIR 128

__device__ float g_F[(size_t)BB * KKK * CCC];
__device__ __nv_bfloat16 g_Fh[(size_t)BB * KKK * CCC];
__device__ __nv_bfloat16 g_Fl[(size_t)BB * KKK * CCC];
__device__ float              g_hmin[(size_t)NPAIR * KKK * 8];
__device__ unsigned long long g_hmask[(size_t)NPAIR * KKK * 8];
__device__ float g_norm2[BB * KKK];
__device__ float g_cx[BB * KKK];
__device__ float g_cy[BB * KKK];
__device__ float g_cz[BB * KKK];
__device__ int   g_idx[BB * KKK];
__device__ int   g_neff[BB];
__device__ int   g_corr[NPAIR * KKK];
__device__ float g_s[NPAIR * KKK];

__device__ __forceinline__ uint32_t smem_u32(const void* p) {
    uint32_t a;
    asm("{ .reg .u64 t; cvta.to.shared.u64 t, %1; cvt.u32.u64 %0, t; }" : "=r"(a) : "l"(p));
    return a;
}
__device__ __forceinline__ void cp_async16(uint32_t saddr, const void* g) {
    asm volatile("cp.async.cg.shared.global [%0], [%1], 16;" :: "r"(saddr), "l"(g));
}
#define CP_COMMIT() asm volatile("cp.async.commit_group;" ::: "memory")

#define LDSM_X4(R0, R1, R2, R3, ADDR) \
    asm volatile("ldmatrix.sync.aligned.m8n8.x4.shared.b16 {%0,%1,%2,%3}, [%4];" \
        : "=r"(R0), "=r"(R1), "=r"(R2), "=r"(R3) : "r"(ADDR))

#define MMA_BF16(D, A, B0, B1) \
    asm volatile("mma.sync.aligned.m16n8k16.row.col.f32.bf16.bf16.f32 " \
        "{%0,%1,%2,%3}, {%4,%5,%6,%7}, {%8,%9}, {%0,%1,%2,%3};" \
        : "+f"((D)[0]), "+f"((D)[1]), "+f"((D)[2]), "+f"((D)[3]) \
        : "r"((A)[0]), "r"((A)[1]), "r"((A)[2]), "r"((A)[3]), "r"(B0), "r"(B1))

#define DELTA 3.0f

// ---- kernel 0: per-batch top-K via bitonic sort on (-attn, idx); zeroes g_norm2 ----
__global__ __launch_bounds__(1024) void topk_kernel(
    const float* __restrict__ attn, const int* __restrict__ num_rt,
    const float* __restrict__ cents, const float* __restrict__ sns)
{
    __shared__ float skey[NNN];
    __shared__ int   sidx[NNN];
    const int b = blockIdx.x, tid = threadIdx.x;
    const int nr = num_rt[b];
    if (tid < KKK) g_norm2[b * KKK + tid] = 0.f;
    skey[tid] = (tid < nr) ? attn[b * NNN + tid] : -1000000000.0f;
    sidx[tid] = tid;
    __syncthreads();
    for (int size = 2; size <= NNN; size <<= 1)
        for (int stride = size >> 1; stride > 0; stride >>= 1) {
            int j = tid ^ stride;
            if (j > tid) {
                float k1 = skey[tid], k2 = skey[j];
                int   i1 = sidx[tid], i2 = sidx[j];
                bool g  = (k1 < k2) || (k1 == k2 && i1 > i2);
                bool dd = ((tid & size) == 0);
                if (g == dd) { skey[tid] = k2; skey[j] = k1; sidx[tid] = i2; sidx[j] = i1; }
            }
            __syncthreads();
        }
    if (tid < KKK) {
        int i = sidx[tid];
        g_idx[b * KKK + tid] = i;
        float sc = sns[b * 4 + 3];
        float cx = cents[(b * NNN + i) * 3 + 0];
        float cy = cents[(b * NNN + i) * 3 + 1];
        float cz = cents[(b * NNN + i) * 3 + 2];
        if (i < nr) {
            cx = cx * sc + sns[b * 4 + 0];
            cy = cy * sc + sns[b * 4 + 1];
            cz = cz * sc + sns[b * 4 + 2];
        }
        g_cx[b * KKK + tid] = cx;
        g_cy[b * KKK + tid] = cy;
        g_cz[b * KKK + tid] = cz;
    }
    if (tid == 0) g_neff[b] = (nr < KKK) ? nr : KKK;
}

// ---- kernel 1: F = gather(rt) @ W_in + b_in (fp32 SIMT, double-buffered) ----
__global__ __launch_bounds__(256) void gemmF_kernel(
    const float* __restrict__ rt, const float* __restrict__ Win,
    const float* __restrict__ bin)
{
    __shared__ float As[2][16][128];
    __shared__ float Bs[2][16][128];
    const int tid = threadIdx.x;
    const int r0 = blockIdx.y * 128;
    const int c0 = blockIdx.x * 128;
    const int tx = tid & 15, ty = tid >> 4;
    const int lrow = tid >> 1, lc = (tid & 1) * 4;
    const int grow = r0 + lrow;
    const float* arow = rt + ((size_t)(grow >> 9) * NNN + g_idx[grow]) * CCC;
    const int q0 = tid, q1 = tid + 256;
    const float* wp0 = Win + (size_t)(q0 >> 5) * CCC + c0 + (q0 & 31) * 4;
    const float* wp1 = Win + (size_t)(q1 >> 5) * CCC + c0 + (q1 & 31) * 4;

    float acc[8][8];
#pragma unroll
    for (int i = 0; i < 8; i++)
#pragma unroll
        for (int j = 0; j < 8; j++) acc[i][j] = 0.f;

    float4 a0 = *(const float4*)(arow + lc);
    float4 a1 = *(const float4*)(arow + lc + 8);
    float4 b0 = *(const float4*)(wp0);
    float4 b1 = *(const float4*)(wp1);

    {
        float (*A)[128] = As[0]; float (*Bb)[128] = Bs[0];
        A[lc + 0][lrow] = a0.x; A[lc + 1][lrow] = a0.y;
        A[lc + 2][lrow] = a0.z; A[lc + 3][lrow] = a0.w;
        A[lc + 8][lrow] = a1.x; A[lc + 9][lrow] = a1.y;
        A[lc +10][lrow] = a1.z; A[lc +11][lrow] = a1.w;
        *(float4*)&Bb[q0 >> 5][(q0 & 31) * 4] = b0;
        *(float4*)&Bb[q1 >> 5][(q1 & 31) * 4] = b1;
    }

    for (int it = 0; it < 16; it++) {
        __syncthreads();
        const int buf = it & 1;
        if (it + 1 < 16) {
            const int cN = (it + 1) * 16;
            a0 = *(const float4*)(arow + cN + lc);
            a1 = *(const float4*)(arow + cN + lc + 8);
            b0 = *(const float4*)(wp0 + (size_t)cN * CCC);
            b1 = *(const float4*)(wp1 + (size_t)cN * CCC);
        }
#pragma unroll
        for (int kk = 0; kk < 16; kk++) {
            float ra[8], rb[8];
            *(float4*)&ra[0] = *(const float4*)&As[buf][kk][ty * 8];
            *(float4*)&ra[4] = *(const float4*)&As[buf][kk][ty * 8 + 4];
            *(float4*)&rb[0] = *(const float4*)&Bs[buf][kk][tx * 8];
            *(float4*)&rb[4] = *(const float4*)&Bs[buf][kk][tx * 8 + 4];
#pragma unroll
            for (int i = 0; i < 8; i++)
#pragma unroll
                for (int j = 0; j < 8; j++) acc[i][j] += ra[i] * rb[j];
        }
        if (it + 1 < 16) {
            float (*A)[128] = As[buf ^ 1]; float (*Bb)[128] = Bs[buf ^ 1];
            A[lc + 0][lrow] = a0.x; A[lc + 1][lrow] = a0.y;
            A[lc + 2][lrow] = a0.z; A[lc + 3][lrow] = a0.w;
            A[lc + 8][lrow] = a1.x; A[lc + 9][lrow] = a1.y;
            A[lc +10][lrow] = a1.z; A[lc +11][lrow] = a1.w;
            *(float4*)&Bb[q0 >> 5][(q0 & 31) * 4] = b0;
            *(float4*)&Bb[q1 >> 5][(q1 & 31) * 4] = b1;
        }
    }
#pragma unroll
    for (int i = 0; i < 8; i++) {
        size_t off = (size_t)(r0 + ty * 8 + i) * CCC + c0 + tx * 8;
        float* dst = g_F + off;
        __nv_bfloat16 hi8[8], lo8[8];
        float ps = 0.f;
#pragma unroll
        for (int j = 0; j < 8; j++) {
            float v = acc[i][j] + bin[c0 + tx * 8 + j];
            dst[j] = v;
            ps += v * v;
            __nv_bfloat16 h = __float2bfloat16(v);
            hi8[j] = h;
            lo8[j] = __float2bfloat16(v - __bfloat162float(h));
        }
        *(uint4*)(g_Fh + off) = *(const uint4*)hi8;
        *(uint4*)(g_Fl + off) = *(const uint4*)lo8;
#pragma unroll
        for (int m = 1; m <= 8; m <<= 1) ps += __shfl_xor_sync(0xffffffffu, ps, m);
        if (tx == 0) atomicAdd(&g_norm2[r0 + ty * 8 + i], ps);
    }
}

// ---- kernel 2: fused 2-pass bf16-split GEMM, 1 sync per chunk ----
#define LDA 40
#define STG (128 * LDA)
#define GDYN_SMEM (9 * STG * 2 + 512)
__global__ __launch_bounds__(256, 2) void gemmG_mma_kernel(
    const int* __restrict__ anc, const int* __restrict__ pos,
    const int* __restrict__ neg)
{
    extern __shared__ char smem[];
    __nv_bfloat16* sAh = (__nv_bfloat16*)smem;
    __nv_bfloat16* sAl = sAh + 3 * STG;
    __nv_bfloat16* sB  = sAh + 6 * STG;
    float* snorm = (float*)(sAh + 9 * STG);

    const int tid = threadIdx.x, lane = tid & 31, wid = tid >> 5;
    const int p = blockIdx.x, mtile = blockIdx.y, ntile = blockIdx.z;
    const int t = p >> 1;
    const int a = anc[t];
    const int c = (p & 1) ? neg[t] : pos[t];

    if (tid < 128) snorm[tid] = g_norm2[c * KKK + ntile * 128 + tid];

    const int m_base = (wid >> 1) * 32;
    const int n_base = (wid & 1) * 64;

    float acc[2][8][4];
#pragma unroll
    for (int mi = 0; mi < 2; mi++)
#pragma unroll
        for (int n8 = 0; n8 < 8; n8++)
#pragma unroll
            for (int r = 0; r < 4; r++) acc[mi][n8][r] = 0.f;

    const int ld_row = tid >> 2, ld_q = (tid & 3) * 8;
    const __nv_bfloat16* gAhi = g_Fh + (size_t)(a * KKK + mtile * 128) * CCC;
    const __nv_bfloat16* gAlo = g_Fl + (size_t)(a * KKK + mtile * 128) * CCC;
    const __nv_bfloat16* gB   = g_Fh + (size_t)(c * KKK + ntile * 128) * CCC;
    const size_t go1 = (size_t)ld_row * CCC + ld_q;
    const size_t go2 = (size_t)(ld_row + 64) * CCC + ld_q;
    const uint32_t so1 = (uint32_t)((ld_row * LDA + ld_q) * 2);
    const uint32_t so2 = (uint32_t)(((ld_row + 64) * LDA + ld_q) * 2);
    const uint32_t sAhu = smem_u32(sAh);
    const uint32_t sAlu = smem_u32(sAl);
    const uint32_t sBu  = smem_u32(sB);

#define ISSUE(KC, ST) do { \
        const int c0 = (KC) * 32; \
        uint32_t dAh = sAhu + (uint32_t)(ST) * (STG * 2); \
        uint32_t dAl = sAlu + (uint32_t)(ST) * (STG * 2); \
        uint32_t dB  = sBu  + (uint32_t)(ST) * (STG * 2); \
        cp_async16(dAh + so1, gAhi + go1 + c0); \
        cp_async16(dAl + so1, gAlo + go1 + c0); \
        cp_async16(dB  + so1, gB   + go1 + c0); \
        cp_async16(dAh + so2, gAhi + go2 + c0); \
        cp_async16(dAl + so2, gAlo + go2 + c0); \
        cp_async16(dB  + so2, gB   + go2 + c0); \
        CP_COMMIT(); \
    } while (0)

    ISSUE(0, 0);
    ISSUE(1, 1);
    for (int kc = 0; kc < 8; kc++) {
        const int buf = kc % 3;
        if (kc < 7) {
            asm volatile("cp.async.wait_group 1;" ::: "memory");
        } else {
            asm volatile("cp.async.wait_group 0;" ::: "memory");
        }
        __syncthreads();
        if (kc + 2 < 8) ISSUE(kc + 2, (kc + 2) % 3);
        const uint32_t sah = sAhu + (uint32_t)buf * (STG * 2);
        const uint32_t sal = sAlu + (uint32_t)buf * (STG * 2);
        const uint32_t sb  = sBu  + (uint32_t)buf * (STG * 2);
#pragma unroll
        for (int ks = 0; ks < 2; ks++) {
            const int k0 = ks * 16;
            const uint32_t arow_off = (uint32_t)(((m_base + (lane & 15)) * LDA + k0 + (lane >> 4) * 8) << 1);
            uint32_t afh[2][4], afl[2][4];
#pragma unroll
            for (int mi = 0; mi < 2; mi++) {
                LDSM_X4(afh[mi][0], afh[mi][1], afh[mi][2], afh[mi][3],
                        sah + arow_off + (uint32_t)((mi * 16 * LDA) << 1));
                LDSM_X4(afl[mi][0], afl[mi][1], afl[mi][2], afl[mi][3],
                        sal + arow_off + (uint32_t)((mi * 16 * LDA) << 1));
            }
            uint32_t bfr[4][4];
#pragma unroll
            for (int nj = 0; nj < 4; nj++) {
                uint32_t addr = sb + (uint32_t)(((n_base + nj * 16 + (lane & 7) + ((lane >> 4) << 3)) * LDA + k0 + ((lane >> 3) & 1) * 8) << 1);
                LDSM_X4(bfr[nj][0], bfr[nj][1], bfr[nj][2], bfr[nj][3], addr);
            }
#pragma unroll
            for (int mi = 0; mi < 2; mi++)
#pragma unroll
                for (int n8 = 0; n8 < 8; n8++) {
                    MMA_BF16(acc[mi][n8], afh[mi], bfr[n8 >> 1][(n8 & 1) * 2], bfr[n8 >> 1][(n8 & 1) * 2 + 1]);
                    MMA_BF16(acc[mi][n8], afl[mi], bfr[n8 >> 1][(n8 & 1) * 2], bfr[n8 >> 1][(n8 & 1) * 2 + 1]);
                }
        }
        __syncthreads();
    }
#undef ISSUE

#pragma unroll
    for (int mi = 0; mi < 2; mi++)
#pragma unroll
        for (int half = 0; half < 2; half++) {
            float kv[16];
            float kmin = 3.4e38f;
            const int lc0 = n_base + (lane & 3) * 2;
#pragma unroll
            for (int n8 = 0; n8 < 8; n8++) {
                float k0v = snorm[lc0 + n8 * 8]     - 2.f * acc[mi][n8][half * 2 + 0];
                float k1v = snorm[lc0 + n8 * 8 + 1] - 2.f * acc[mi][n8][half * 2 + 1];
                kv[n8 * 2]     = k0v;
                kv[n8 * 2 + 1] = k1v;
                kmin = fminf(kmin, fminf(k0v, k1v));
            }
            kmin = fminf(kmin, __shfl_xor_sync(0xffffffffu, kmin, 1));
            kmin = fminf(kmin, __shfl_xor_sync(0xffffffffu, kmin, 2));
            const float thr = kmin + DELTA;
            unsigned long long mk = 0ull;
#pragma unroll
            for (int n8 = 0; n8 < 8; n8++) {
                if (kv[n8 * 2]     <= thr) mk |= 1ull << (n8 * 8 + (lane & 3) * 2);
                if (kv[n8 * 2 + 1] <= thr) mk |= 1ull << (n8 * 8 + (lane & 3) * 2 + 1);
            }
            mk |= __shfl_xor_sync(0xffffffffu, mk, 1);
            mk |= __shfl_xor_sync(0xffffffffu, mk, 2);
            if ((lane & 3) == 0) {
                int grow = mtile * 128 + m_base + mi * 16 + half * 8 + (lane >> 2);
                int hidx = ntile * 2 + (wid & 1);
                size_t o = ((size_t)p * KKK + grow) * 8 + hidx;
                g_hmin[o]  = kmin;
                g_hmask[o] = mk;
            }
        }
}

// ---- kernel 2b: exact argmin, all loads hoisted (1 warp per row) ----
__global__ __launch_bounds__(256) void refine_kernel(
    const int* __restrict__ anc, const int* __restrict__ pos,
    const int* __restrict__ neg)
{
    const int p = blockIdx.x, tid = threadIdx.x;
    const int t = p >> 1;
    const int a = anc[t];
    const int c = (p & 1) ? neg[t] : pos[t];
    const int wid = tid >> 5, lane = tid & 31;
    const float* nrm = g_norm2 + c * KKK;

    const int r = blockIdx.y * 8 + wid;
    const size_t base = ((size_t)p * KKK + r) * 8;

    const float* fa = g_F + ((size_t)a * KKK + r) * CCC;
    const float4 fa0 = ((const float4*)fa)[lane * 2];
    const float4 fa1 = ((const float4*)fa)[lane * 2 + 1];
    float hm = (lane < 8) ? g_hmin[base + lane] : 3.4e38f;
    unsigned long long hmk = (lane < 8) ? g_hmask[base + lane] : 0ull;

    float bk = hm;
#pragma unroll
    for (int m = 4; m >= 1; m >>= 1) bk = fminf(bk, __shfl_xor_sync(0xffffffffu, bk, m));
    bk = __shfl_sync(0xffffffffu, bk, 0);
    const float thr = bk + DELTA;

    float bestk = 3.4e38f; int bestc = 0; float bestd = 0.f;
#pragma unroll 1
    for (int h = 0; h < 8; h++) {
        float mh = __shfl_sync(0xffffffffu, hm, h);
        if (mh > thr) continue;
        unsigned long long mk = __shfl_sync(0xffffffffu, hmk, h);
        const int colbase = h * 64;
        while (mk) {
            int b = __ffsll(mk) - 1; mk &= mk - 1;
            int col = colbase + b;
            const float4* fb4 = (const float4*)(g_F + ((size_t)c * KKK + col) * CCC);
            float4 fb0 = fb4[lane * 2];
            float4 fb1 = fb4[lane * 2 + 1];
            float sd = fa0.x * fb0.x + fa0.y * fb0.y + fa0.z * fb0.z + fa0.w * fb0.w
                     + fa1.x * fb1.x + fa1.y * fb1.y + fa1.z * fb1.z + fa1.w * fb1.w;
#pragma unroll
            for (int mm = 16; mm >= 1; mm >>= 1) sd += __shfl_xor_sync(0xffffffffu, sd, mm);
            float ek = nrm[col] - 2.f * sd;
            if (ek < bestk) { bestk = ek; bestc = col; bestd = sd; }
        }
    }
    if (lane == 0) {
        float na = sqrtf(g_norm2[a * KKK + r]);
        float nb = sqrtf(nrm[bestc]);
        g_s[p * KKK + r]    = fmaxf(bestd / (na * nb + 1e-8f), 0.f);
        g_corr[p * KKK + r] = bestc;
    }
}

// ---- kernel 3: geo bitmask (sqrt-free) + power iteration (dense float4) + sort + MLP ----
__global__ __launch_bounds__(512) void pair_kernel(
    const int* __restrict__ anc, const int* __restrict__ pos,
    const int* __restrict__ neg,
    const float* __restrict__ W1, const float* __restrict__ b1,
    const float* __restrict__ W2, const float* __restrict__ b2,
    float* __restrict__ out, int out_size)
{
    __shared__ unsigned int smask[KKK * 16];
    __shared__ float bufA[KKK * 3];
    __shared__ float bufB[KKK * 3];
    __shared__ float red[16];

    const int p = blockIdx.x, tid = threadIdx.x;
    const int t = p >> 1, n = p & 1;
    const int a = anc[t];
    const int c = n ? neg[t] : pos[t];
    const int neffa = g_neff[a], neffc = g_neff[c];
    const int wid = tid >> 5, lane = tid & 31;

    bufA[tid]           = g_cx[a * KKK + tid];
    bufA[KKK + tid]     = g_cy[a * KKK + tid];
    bufA[2 * KKK + tid] = g_cz[a * KKK + tid];
    {
        int j = g_corr[p * KKK + tid];
        bufB[tid]           = g_cx[c * KKK + j];
        bufB[KKK + tid]     = g_cy[c * KKK + j];
        bufB[2 * KKK + tid] = g_cz[c * KKK + j];
    }
    float sk = g_s[p * KKK + tid];
    __syncthreads();

    // geo test without sqrt: |sqrt(x)-sqrt(y)| < 0.5  <=>  s<0 || s^2 < 4xy, s=x+y-0.25
    for (int kr = 0; kr < 32; kr++) {
        int k = wid * 32 + kr;
        float akx = bufA[k], aky = bufA[KKK + k], akz = bufA[2 * KKK + k];
        float qkx = bufB[k], qky = bufB[KKK + k], qkz = bufB[2 * KKK + k];
        bool rowvalid = (k < neffa);
#pragma unroll 4
        for (int ch = 0; ch < 16; ch++) {
            int l = ch * 32 + lane;
            float dx = akx - bufA[l], dy = aky - bufA[KKK + l], dz = akz - bufA[2 * KKK + l];
            float x = dx * dx + dy * dy + dz * dz + 1e-12f;
            float ex = qkx - bufB[l], ey = qky - bufB[KKK + l], ez = qkz - bufB[2 * KKK + l];
            float y = ex * ex + ey * ey + ez * ez + 1e-12f;
            float s = x + y - 0.25f;
            bool near = (s < 0.f) || (s * s < 4.f * x * y);
            bool geo = near && rowvalid && (l < neffc) && (l != k);
            unsigned bits = __ballot_sync(0xffffffffu, geo);
            if (lane == 0) smask[k * 16 + ch] = bits;
        }
    }
    __syncthreads();

    float* sm_u = bufA;
    float v = (float)(1.0 / sqrt((double)KKK));
    for (int it = 0; it < 20; it++) {
        sm_u[tid] = sk * v;
        __syncthreads();
        float a0 = 0.f, a1 = 0.f, a2 = 0.f, a3 = 0.f;
        const unsigned* mrow = &smask[tid * 16];
        const float4* u4 = (const float4*)sm_u;
#pragma unroll 4
        for (int w = 0; w < 16; w++) {
            unsigned bits = mrow[w];
#pragma unroll
            for (int q = 0; q < 8; q++) {
                float4 u = u4[w * 8 + q];
                if (bits & (1u << (q * 4 + 0))) a0 += u.x;
                if (bits & (1u << (q * 4 + 1))) a1 += u.y;
                if (bits & (1u << (q * 4 + 2))) a2 += u.z;
                if (bits & (1u << (q * 4 + 3))) a3 += u.w;
            }
        }
        float wv = sk * ((a0 + a1) + (a2 + a3));
        float ss = wv * wv;
#pragma unroll
        for (int m = 16; m >= 1; m >>= 1) ss += __shfl_xor_sync(0xffffffffu, ss, m);
        if (lane == 0) red[wid] = ss;
        __syncthreads();
        float tot = 0.f;
#pragma unroll
        for (int w = 0; w < 16; w++) tot += red[w];
        v = wv / (sqrtf(tot) + 1e-8f);
    }

    float* sv = bufB;
    __syncthreads();
    sv[tid] = v;
    __syncthreads();
    for (int size = 2; size <= KKK; size <<= 1)
        for (int stride = size >> 1; stride > 0; stride >>= 1) {
            int jj = tid ^ stride;
            if (jj > tid) {
                float x1 = sv[tid], x2 = sv[jj];
                bool g  = (x1 < x2);
                bool dd = ((tid & size) == 0);
                if (g == dd) { sv[tid] = x2; sv[jj] = x1; }
            }
            __syncthreads();
        }

    float hacc = b1[tid];
    {
        const float4* sv4 = (const float4*)sv;
#pragma unroll 4
        for (int l4 = 0; l4 < 128; l4++) {
            float4 e = sv4[l4];
            hacc += e.x * W1[(size_t)(l4 * 4 + 0) * KKK + tid];
            hacc += e.y * W1[(size_t)(l4 * 4 + 1) * KKK + tid];
            hacc += e.z * W1[(size_t)(l4 * 4 + 2) * KKK + tid];
            hacc += e.w * W1[(size_t)(l4 * 4 + 3) * KKK + tid];
        }
    }
    float h = fmaxf(hacc, 0.f);
    float contrib = h * W2[tid];
#pragma unroll
    for (int m = 16; m >= 1; m >>= 1) contrib += __shfl_xor_sync(0xffffffffu, contrib, m);
    if (lane == 0) red[wid] = contrib;
    __syncthreads();
    if (tid == 0) {
        float x = 0.f;
        for (int w = 0; w < 16; w++) x += red[w];
        float score = 1.f / (1.f + expf(-(x + b2[0])));
        out[p] = score;
        if (NPAIR + p < out_size) out[NPAIR + p] = (n == 0) ? 1.f : 0.f;
    }
}

extern "C" void kernel_launch(void* const* d_in, const int* in_sizes, int n_in,
                              void* d_out, int out_size) {
    const float* rt    = (const float*)d_in[0];
    const float* cents = (const float*)d_in[1];
    const float* attn  = (const float*)d_in[2];
    const float* sns   = (const float*)d_in[3];
    const int*   nrt   = (const int*)d_in[4];
    const int*   anc   = (const int*)d_in[5];
    const int*   pos   = (const int*)d_in[6];
    const int*   neg   = (const int*)d_in[7];
    const float* Win   = (const float*)d_in[8];
    const float* bin   = (const float*)d_in[9];
    const float* W1    = (const float*)d_in[10];
    const float* b1    = (const float*)d_in[11];
    const float* W2    = (const float*)d_in[12];
    const float* b2    = (const float*)d_in[13];
    float* out = (float*)d_out;

    cudaFuncSetAttribute(gemmG_mma_kernel, cudaFuncAttributeMaxDynamicSharedMemorySize, GDYN_SMEM);

    topk_kernel<<<BB, 1024>>>(attn, nrt, cents, sns);
    gemmF_kernel<<<dim3(CCC / 128, BB * KKK / 128), 256>>>(rt, Win, bin);
    gemmG_mma_kernel<<<dim3(NPAIR, 4, 4), 256, GDYN_SMEM>>>(anc, pos, neg);
    refine_kernel<<<dim3(NPAIR, 64), 256>>>(anc, pos, neg);
    pair_kernel<<<NPAIR, 512>>>(anc, pos, neg, W1, b1, W2, b2, out, out_size);
}